// round 6
// baseline (speedup 1.0000x reference)
#include <cuda_runtime.h>
#include <cuda_fp16.h>
#include <mma.h>
#include <math.h>
#include <stdint.h>

using namespace nvcuda;

// Problem constants
#define CHUNKS     8
#define CSIZE      512
#define DIM        4096
#define NROWS      16384
#define INV_TEMP   (1.0f / 0.15f)
#define SINK_ITERS 5

// Scratch (device globals — no runtime allocation allowed)
__device__ float  g_qlog[CHUNKS * CSIZE * CSIZE];      // 8 MB sinkhorn buffer
__device__ float  g_p[64];                             // 8x8 chunk perm
__device__ __half g_qh[CHUNKS * CSIZE * CSIZE];        // 4 MB   Q fp16
__device__ __half g_yh[(size_t)NROWS * DIM];           // 128 MB Y fp16

// ---------------------------------------------------------------------------
// Sinkhorn on 8x8 chunk logits
// ---------------------------------------------------------------------------
__global__ void sinkhorn_chunk_kernel(const float* __restrict__ logits,
                                      float* __restrict__ p_out) {
    __shared__ float s[64];
    int t = threadIdx.x;
    int r = t >> 3;
    int c = t & 7;
    float v = logits[t] * INV_TEMP;

    for (int it = 0; it < SINK_ITERS; ++it) {
        s[t] = v;
        __syncthreads();
        float mx = -1e30f;
        #pragma unroll
        for (int j = 0; j < 8; ++j) mx = fmaxf(mx, s[r * 8 + j]);
        float sm = 0.0f;
        #pragma unroll
        for (int j = 0; j < 8; ++j) sm += expf(s[r * 8 + j] - mx);
        v -= mx + logf(sm);
        __syncthreads();

        s[t] = v;
        __syncthreads();
        mx = -1e30f;
        #pragma unroll
        for (int j = 0; j < 8; ++j) mx = fmaxf(mx, s[j * 8 + c]);
        sm = 0.0f;
        #pragma unroll
        for (int j = 0; j < 8; ++j) sm += expf(s[j * 8 + c] - mx);
        v -= mx + logf(sm);
        __syncthreads();
    }
    p_out[t] = expf(v);
}

// ---------------------------------------------------------------------------
// Row LSE pass (over last axis). Block per row, 128 threads.
// ---------------------------------------------------------------------------
__global__ void lse_rows_kernel(const float* __restrict__ in,
                                float* __restrict__ out, float scale) {
    int row = blockIdx.x;
    const float* p = in  + (size_t)row * CSIZE;
    float*       q = out + (size_t)row * CSIZE;
    int t = threadIdx.x;

    float v[4];
    float mx = -1e30f;
    #pragma unroll
    for (int i = 0; i < 4; ++i) {
        v[i] = p[t + i * 128] * scale;
        mx = fmaxf(mx, v[i]);
    }

    __shared__ float red[128];
    red[t] = mx;
    __syncthreads();
    #pragma unroll
    for (int s2 = 64; s2 > 0; s2 >>= 1) {
        if (t < s2) red[t] = fmaxf(red[t], red[t + s2]);
        __syncthreads();
    }
    mx = red[0];
    __syncthreads();

    float sm = 0.0f;
    #pragma unroll
    for (int i = 0; i < 4; ++i) sm += expf(v[i] - mx);
    red[t] = sm;
    __syncthreads();
    #pragma unroll
    for (int s2 = 64; s2 > 0; s2 >>= 1) {
        if (t < s2) red[t] += red[t + s2];
        __syncthreads();
    }
    float lse = mx + logf(red[0]);

    #pragma unroll
    for (int i = 0; i < 4; ++i) q[t + i * 128] = v[i] - lse;
}

// ---------------------------------------------------------------------------
// Column LSE pass (over axis -2). Grid = 8 chunks * 16 colgroups, 256 thr.
// Final pass (apply_exp) writes exp(q - lse) as fp16 into qh.
// ---------------------------------------------------------------------------
__global__ void lse_cols_kernel(float* __restrict__ buf,
                                __half* __restrict__ qh, int apply_exp) {
    int chunk = blockIdx.x >> 4;
    int colbase = (blockIdx.x & 15) * 32;
    int t = threadIdx.x;
    int col = t & 31;
    int rg  = t >> 5;                 // 0..7
    size_t base_i = (size_t)chunk * CSIZE * CSIZE + colbase + col;
    float* base = buf + base_i;

    __shared__ float red[8][32];

    float mx = -1e30f;
    for (int r = rg; r < CSIZE; r += 8) mx = fmaxf(mx, base[(size_t)r * CSIZE]);
    red[rg][col] = mx;
    __syncthreads();
    if (rg == 0) {
        float m = red[0][col];
        #pragma unroll
        for (int j = 1; j < 8; ++j) m = fmaxf(m, red[j][col]);
        red[0][col] = m;
    }
    __syncthreads();
    mx = red[0][col];
    __syncthreads();

    float sm = 0.0f;
    for (int r = rg; r < CSIZE; r += 8) sm += expf(base[(size_t)r * CSIZE] - mx);
    red[rg][col] = sm;
    __syncthreads();
    if (rg == 0) {
        float s = red[0][col];
        #pragma unroll
        for (int j = 1; j < 8; ++j) s += red[j][col];
        red[0][col] = s;
    }
    __syncthreads();
    float lse = mx + logf(red[0][col]);

    if (apply_exp) {
        __half* qbase = qh + base_i;
        for (int r = rg; r < CSIZE; r += 8)
            qbase[(size_t)r * CSIZE] =
                __float2half(expf(base[(size_t)r * CSIZE] - lse));
    } else {
        for (int r = rg; r < CSIZE; r += 8)
            base[(size_t)r * CSIZE] -= lse;
    }
}

// ---------------------------------------------------------------------------
// Chunk mix producing fp16: y = P @ x per (b, d)
// ---------------------------------------------------------------------------
__global__ void mix_half_kernel(const float* __restrict__ x,
                                __half* __restrict__ yh,
                                const float* __restrict__ P) {
    __shared__ float p[64];
    if (threadIdx.x < 64) p[threadIdx.x] = P[threadIdx.x];
    __syncthreads();

    int idx = blockIdx.x * blockDim.x + threadIdx.x;
    int b  = idx >> 7;
    int d4 = idx & 127;

    const float4* xb = (const float4*)(x + (size_t)b * DIM) + d4;

    float4 xv[8];
    #pragma unroll
    for (int j = 0; j < 8; ++j) xv[j] = xb[(size_t)j * 128];

    #pragma unroll
    for (int i = 0; i < 8; ++i) {
        float4 acc = make_float4(0.f, 0.f, 0.f, 0.f);
        #pragma unroll
        for (int j = 0; j < 8; ++j) {
            float w = p[i * 8 + j];
            acc.x += w * xv[j].x;
            acc.y += w * xv[j].y;
            acc.z += w * xv[j].z;
            acc.w += w * xv[j].w;
        }
        __half2 h01 = __floats2half2_rn(acc.x, acc.y);
        __half2 h23 = __floats2half2_rn(acc.z, acc.w);
        size_t e = (size_t)b * DIM + (size_t)i * CSIZE + (size_t)d4 * 4;  // even
        ((__half2*)yh)[e >> 1]       = h01;
        ((__half2*)yh)[(e >> 1) + 1] = h23;
    }
}

// ---------------------------------------------------------------------------
// WMMA (HMMA) GEMM, fp16 in / fp32 accum.
// CTA tile 128x256, K-step 32, 3-stage cp.async pipeline, 512 threads
// (16 warps = 4M x 4N, warp tile 32x64).
// ---------------------------------------------------------------------------
#define BM      128
#define BN      256
#define BK      32
#define NKITER  16          // 512 / 32
#define LDS_PAD 40          // padded row stride (elems): 80 B, multiple of 16 B
#define A_STAGE (BM * LDS_PAD)              // elems per A stage (5120)
#define B_STAGE (BN * LDS_PAD)              // elems per B stage (10240)
#define SMEM_BYTES ((3 * (A_STAGE + B_STAGE)) * 2)   // 92160 B

__device__ __forceinline__ void cp16(uint32_t dst, const void* src) {
    asm volatile("cp.async.cg.shared.global [%0], [%1], 16;" :: "r"(dst), "l"(src));
}

__global__ __launch_bounds__(512, 1)
void wmma_gemm_kernel(const __half* __restrict__ yh,
                      const __half* __restrict__ qh,
                      float* __restrict__ out) {
    extern __shared__ __half smem[];
    __half* sA = smem;                       // 3 stages of BM x BK (padded)
    __half* sB = smem + 3 * A_STAGE;         // 3 stages of BN x BK (padded)

    const int c  = blockIdx.z;
    const int m0 = blockIdx.y * BM;
    const int n0 = blockIdx.x * BN;
    const int tid = threadIdx.x;
    const int wid = tid >> 5;
    const int wm  = wid >> 2;      // 0..3 -> 32-row slab
    const int wn  = wid & 3;       // 0..3 -> 64-col slab

    wmma::fragment<wmma::accumulator, 16, 16, 16, float> acc[2][4];
    #pragma unroll
    for (int i = 0; i < 2; ++i)
        #pragma unroll
        for (int j = 0; j < 4; ++j) wmma::fill_fragment(acc[i][j], 0.0f);

    // Load assignment (per stage): A = 512 16B-units (1/thread),
    //                              B = 1024 16B-units (2/thread)
    const int ra  = tid >> 2;            // A row 0..127
    const int ca  = tid & 3;             // A col-chunk 0..3
    const int rb0 = tid >> 2;            // B row (unit tid)
    const int cb0 = tid & 3;
    const int rb1 = (tid + 512) >> 2;    // B row (unit tid+512)
    const int cb1 = (tid + 512) & 3;

    uint32_t aDst[3], bDst0[3], bDst1[3];
    #pragma unroll
    for (int s = 0; s < 3; ++s) {
        aDst[s]  = (uint32_t)__cvta_generic_to_shared(
                       &sA[s * A_STAGE + ra * LDS_PAD + ca * 8]);
        bDst0[s] = (uint32_t)__cvta_generic_to_shared(
                       &sB[s * B_STAGE + rb0 * LDS_PAD + cb0 * 8]);
        bDst1[s] = (uint32_t)__cvta_generic_to_shared(
                       &sB[s * B_STAGE + rb1 * LDS_PAD + cb1 * 8]);
    }

    const __half* Abase = yh + (size_t)m0 * DIM + (size_t)c * CSIZE;
    const __half* Bbase = qh + (size_t)c * CSIZE * CSIZE + (size_t)n0 * CSIZE;

    auto issue_loads = [&](int i, int s) {
        int kk = i * BK;
        cp16(aDst[s],  Abase + (size_t)ra  * DIM   + kk + ca  * 8);
        cp16(bDst0[s], Bbase + (size_t)rb0 * CSIZE + kk + cb0 * 8);
        cp16(bDst1[s], Bbase + (size_t)rb1 * CSIZE + kk + cb1 * 8);
        asm volatile("cp.async.commit_group;" ::: "memory");
    };

    issue_loads(0, 0);
    issue_loads(1, 1);

    for (int i = 0; i < NKITER; ++i) {
        int s = i % 3;
        asm volatile("cp.async.wait_group 1;" ::: "memory");
        __syncthreads();

        if (i + 2 < NKITER) issue_loads(i + 2, (i + 2) % 3);
        else asm volatile("cp.async.commit_group;" ::: "memory");

        const __half* As = &sA[s * A_STAGE];
        const __half* Bs = &sB[s * B_STAGE];

        #pragma unroll
        for (int k2 = 0; k2 < 2; ++k2) {
            wmma::fragment<wmma::matrix_a, 16, 16, 16, __half, wmma::row_major> af[2];
            wmma::fragment<wmma::matrix_b, 16, 16, 16, __half, wmma::col_major> bf[4];
            #pragma unroll
            for (int mi = 0; mi < 2; ++mi)
                wmma::load_matrix_sync(af[mi],
                    &As[(wm * 32 + mi * 16) * LDS_PAD + k2 * 16], LDS_PAD);
            #pragma unroll
            for (int nj = 0; nj < 4; ++nj)
                wmma::load_matrix_sync(bf[nj],
                    &Bs[(wn * 64 + nj * 16) * LDS_PAD + k2 * 16], LDS_PAD);
            #pragma unroll
            for (int mi = 0; mi < 2; ++mi)
                #pragma unroll
                for (int nj = 0; nj < 4; ++nj)
                    wmma::mma_sync(acc[mi][nj], af[mi], bf[nj], acc[mi][nj]);
        }
        __syncthreads();
    }

    // epilogue: direct store to out
    #pragma unroll
    for (int mi = 0; mi < 2; ++mi) {
        #pragma unroll
        for (int nj = 0; nj < 4; ++nj) {
            float* dst = out + (size_t)(m0 + wm * 32 + mi * 16) * DIM
                             + (size_t)c * CSIZE + n0 + wn * 64 + nj * 16;
            wmma::store_matrix_sync(dst, acc[mi][nj], DIM, wmma::mem_row_major);
        }
    }
}

// ---------------------------------------------------------------------------
// Launch
// ---------------------------------------------------------------------------
extern "C" void kernel_launch(void* const* d_in, const int* in_sizes, int n_in,
                              void* d_out, int out_size) {
    const float* x            = (const float*)d_in[0];
    const float* chunk_logits = (const float*)d_in[1];
    const float* intra_logits = (const float*)d_in[2];
    float*       out          = (float*)d_out;

    float*  qlog; cudaGetSymbolAddress((void**)&qlog, g_qlog);
    float*  p;    cudaGetSymbolAddress((void**)&p,    g_p);
    __half* qh;   cudaGetSymbolAddress((void**)&qh,   g_qh);
    __half* yh;   cudaGetSymbolAddress((void**)&yh,   g_yh);

    // 1) 8x8 chunk sinkhorn
    sinkhorn_chunk_kernel<<<1, 64>>>(chunk_logits, p);

    // 2) intra sinkhorn (5x row+col); exp + fp16 cast fused into final col pass
    lse_rows_kernel<<<CHUNKS * CSIZE, 128>>>(intra_logits, qlog, INV_TEMP);
    lse_cols_kernel<<<CHUNKS * 16, 256>>>(qlog, qh, 0);
    for (int it = 1; it < SINK_ITERS; ++it) {
        lse_rows_kernel<<<CHUNKS * CSIZE, 128>>>(qlog, qlog, 1.0f);
        lse_cols_kernel<<<CHUNKS * 16, 256>>>(qlog, qh, (it == SINK_ITERS - 1) ? 1 : 0);
    }

    // 3) chunk mix -> fp16 Y
    mix_half_kernel<<<(NROWS * 128) / 256, 256>>>(x, yh, p);

    // 4) tensor-core GEMM (fp16 in, fp32 accum): out = Y Q^T per chunk
    cudaFuncSetAttribute(wmma_gemm_kernel,
                         cudaFuncAttributeMaxDynamicSharedMemorySize, SMEM_BYTES);
    dim3 grid(BN == 256 ? 2 : 4, NROWS / BM, CHUNKS);
    wmma_gemm_kernel<<<grid, 512, SMEM_BYTES>>>(yh, qh, out);
}